// round 8
// baseline (speedup 1.0000x reference)
#include <cuda_runtime.h>
#include <cuda_bf16.h>
#include <cstdint>

#define SEQ 2048
#define DIM 64
#define NBH 32   // B*H
#define RS 72    // smem row stride (bf16) for 64-wide rows
#define RS2 136  // smem row stride (bf16) for 128-wide rows

// Scratch (device globals; no allocs allowed)
__device__ __nv_bfloat16 g_qh[(size_t)NBH * SEQ * DIM];
__device__ __nv_bfloat16 g_ql[(size_t)NBH * SEQ * DIM];
__device__ __nv_bfloat16 g_kh[(size_t)NBH * SEQ * DIM];
__device__ __nv_bfloat16 g_kl[(size_t)NBH * SEQ * DIM];
__device__ __nv_bfloat16 g_vt_hi[(size_t)NBH * DIM * SEQ];
__device__ __nv_bfloat16 g_vt_lo[(size_t)NBH * DIM * SEQ];
__device__ __nv_bfloat16 g_ah[(size_t)NBH * SEQ * SEQ];   // unnormalized exp, hi
__device__ __nv_bfloat16 g_al[(size_t)NBH * SEQ * SEQ];   // unnormalized exp, lo
__device__ uint32_t g_mbits[(size_t)SEQ * (SEQ / 32)];

// ---------------- helpers ----------------
__device__ __forceinline__ uint32_t smem_u32(const void* p) {
    uint32_t a;
    asm("{ .reg .u64 t; cvta.to.shared.u64 t, %1; cvt.u32.u64 %0, t; }" : "=r"(a) : "l"(p));
    return a;
}
__device__ __forceinline__ void ldsm_x4(uint32_t r[4], uint32_t addr) {
    asm volatile("ldmatrix.sync.aligned.m8n8.x4.shared.b16 {%0,%1,%2,%3}, [%4];"
        : "=r"(r[0]), "=r"(r[1]), "=r"(r[2]), "=r"(r[3]) : "r"(addr));
}
__device__ __forceinline__ void mma2(float c[4], const uint32_t a[4],
                                     uint32_t b0, uint32_t b1) {
    asm volatile(
        "mma.sync.aligned.m16n8k16.row.col.f32.bf16.bf16.f32 "
        "{%0,%1,%2,%3}, {%4,%5,%6,%7}, {%8,%9}, {%0,%1,%2,%3};"
        : "+f"(c[0]), "+f"(c[1]), "+f"(c[2]), "+f"(c[3])
        : "r"(a[0]), "r"(a[1]), "r"(a[2]), "r"(a[3]), "r"(b0), "r"(b1));
}
__device__ __forceinline__ void cp16(uint32_t dst, const void* src) {
    asm volatile("{ .reg .u64 g; cvta.to.global.u64 g, %1; cp.async.cg.shared.global [%0], [g], 16; }"
        :: "r"(dst), "l"(src) : "memory");
}
#define CP_COMMIT asm volatile("cp.async.commit_group;" ::: "memory")
#define CP_WAIT0  asm volatile("cp.async.wait_group 0;" ::: "memory")

__device__ __forceinline__ void split4(float4 v, uint32_t& h01, uint32_t& h23,
                                       uint32_t& l01, uint32_t& l23) {
    __nv_bfloat16 h0 = __float2bfloat16_rn(v.x);
    __nv_bfloat16 h1 = __float2bfloat16_rn(v.y);
    __nv_bfloat16 h2 = __float2bfloat16_rn(v.z);
    __nv_bfloat16 h3 = __float2bfloat16_rn(v.w);
    __nv_bfloat16 q0 = __float2bfloat16_rn(v.x - __bfloat162float(h0));
    __nv_bfloat16 q1 = __float2bfloat16_rn(v.y - __bfloat162float(h1));
    __nv_bfloat16 q2 = __float2bfloat16_rn(v.z - __bfloat162float(h2));
    __nv_bfloat16 q3 = __float2bfloat16_rn(v.w - __bfloat162float(h3));
    h01 = (uint32_t)__bfloat16_as_ushort(h0) | ((uint32_t)__bfloat16_as_ushort(h1) << 16);
    h23 = (uint32_t)__bfloat16_as_ushort(h2) | ((uint32_t)__bfloat16_as_ushort(h3) << 16);
    l01 = (uint32_t)__bfloat16_as_ushort(q0) | ((uint32_t)__bfloat16_as_ushort(q1) << 16);
    l23 = (uint32_t)__bfloat16_as_ushort(q2) | ((uint32_t)__bfloat16_as_ushort(q3) << 16);
}
__device__ __forceinline__ void pack2(float a, float b, uint32_t& h, uint32_t& lo) {
    __nv_bfloat16 h0 = __float2bfloat16_rn(a), h1 = __float2bfloat16_rn(b);
    __nv_bfloat16 l0 = __float2bfloat16_rn(a - __bfloat162float(h0));
    __nv_bfloat16 l1 = __float2bfloat16_rn(b - __bfloat162float(h1));
    h  = (uint32_t)__bfloat16_as_ushort(h0) | ((uint32_t)__bfloat16_as_ushort(h1) << 16);
    lo = (uint32_t)__bfloat16_as_ushort(l0) | ((uint32_t)__bfloat16_as_ushort(l1) << 16);
}
__device__ __forceinline__ float2 pairval(uint32_t h, uint32_t l, float iv) {
    float2 fh = __bfloat1622float2(*(__nv_bfloat162*)&h);
    float2 fl = __bfloat1622float2(*(__nv_bfloat162*)&l);
    return make_float2((fh.x + fl.x) * iv, (fh.y + fl.y) * iv);
}

// ---------------- prep kernels ----------------
__global__ __launch_bounds__(256) void mask_compress(const int* __restrict__ mask) {
    int w = blockIdx.x * 256 + threadIdx.x;
    const int4* m4 = (const int4*)mask + (size_t)w * 8;
    uint32_t b = 0;
    #pragma unroll
    for (int i = 0; i < 8; i++) {
        int4 v = m4[i];
        b |= (uint32_t)(v.x != 0) << (i * 4 + 0);
        b |= (uint32_t)(v.y != 0) << (i * 4 + 1);
        b |= (uint32_t)(v.z != 0) << (i * 4 + 2);
        b |= (uint32_t)(v.w != 0) << (i * 4 + 3);
    }
    g_mbits[w] = b;
}

__global__ __launch_bounds__(256) void split_prep(const float* __restrict__ X,
                                                  __nv_bfloat16* __restrict__ hi,
                                                  __nv_bfloat16* __restrict__ lo,
                                                  float scale) {
    size_t i = (size_t)blockIdx.x * 256 + threadIdx.x;
    float4 v = ((const float4*)X)[i];
    v.x *= scale; v.y *= scale; v.z *= scale; v.w *= scale;
    uint32_t h01, h23, l01, l23;
    split4(v, h01, h23, l01, l23);
    ((uint2*)hi)[i] = make_uint2(h01, h23);
    ((uint2*)lo)[i] = make_uint2(l01, l23);
}

__global__ __launch_bounds__(256) void vt_prep(const float* __restrict__ V) {
    __shared__ float tile[128][DIM + 1];
    const int bh = blockIdx.y;
    const int k0 = blockIdx.x * 128;
    const int tid = threadIdx.x;

    const float4* V4 = (const float4*)(V + ((size_t)bh * SEQ + k0) * DIM);
    #pragma unroll
    for (int p = 0; p < 8; p++) {
        int lin = tid + p * 256;
        int r = lin >> 4, j = lin & 15;
        float4 v = V4[lin];
        tile[r][j * 4 + 0] = v.x; tile[r][j * 4 + 1] = v.y;
        tile[r][j * 4 + 2] = v.z; tile[r][j * 4 + 3] = v.w;
    }
    __syncthreads();
    #pragma unroll
    for (int p = 0; p < 32; p++) {
        int lin = tid + p * 256;
        int n = lin >> 7, k = lin & 127;
        float x = tile[k][n];
        __nv_bfloat16 h = __float2bfloat16_rn(x);
        __nv_bfloat16 l = __float2bfloat16_rn(x - __bfloat162float(h));
        size_t o = ((size_t)bh * DIM + n) * SEQ + k0 + k;
        g_vt_hi[o] = h;
        g_vt_lo[o] = l;
    }
}

// ---------------- fused flash-attention strip kernel ----------------
// smem layout (bytes):
//   Q hi [0, 18432)          Q lo [18432, 36864)
//   K buf0 hi 36864 lo 55296 ; K buf1 hi 73728 lo 92160
//   V buf0 hi 110592 lo 128000 ; V buf1 hi 145408 lo 162816
//   total 180224
#define SQH 0u
#define SQL 18432u
#define SKB 36864u
#define SKSZ 36864u
#define SVB 110592u
#define SVSZ 34816u

__global__ __launch_bounds__(256, 1) void fa_strip(float* __restrict__ attn,
                                                   float* __restrict__ out) {
    extern __shared__ char sm[];
    __shared__ float sinv[128];
    const uint32_t sb = smem_u32(sm);
    const int tid = threadIdx.x, w = tid >> 5, l = tid & 31;
    const int m0 = blockIdx.x * 128, bh = blockIdx.y;

    const uint4* Qh4 = (const uint4*)(g_qh + ((size_t)bh * SEQ + m0) * DIM);
    const uint4* Ql4 = (const uint4*)(g_ql + ((size_t)bh * SEQ + m0) * DIM);
    const uint4* Kh4 = (const uint4*)(g_kh + (size_t)bh * SEQ * DIM);
    const uint4* Kl4 = (const uint4*)(g_kl + (size_t)bh * SEQ * DIM);
    const uint4* Vh4 = (const uint4*)(g_vt_hi + (size_t)bh * DIM * SEQ);
    const uint4* Vl4 = (const uint4*)(g_vt_lo + (size_t)bh * DIM * SEQ);

    // ---- async copy issue helpers ----
    auto issue_k = [&](int kt, uint32_t dhi) {
        const uint4* kh = Kh4 + (size_t)kt * 1024;
        const uint4* kl = Kl4 + (size_t)kt * 1024;
        #pragma unroll
        for (int p = 0; p < 4; p++) {
            int lin = tid + p * 256;
            int r = lin >> 3, c = lin & 7;
            uint32_t off = (uint32_t)(r * RS + c * 8) * 2;
            cp16(dhi + off, kh + lin);
            cp16(dhi + 18432 + off, kl + lin);
        }
    };
    auto issue_v = [&](int kt, uint32_t dhi) {
        #pragma unroll
        for (int p = 0; p < 4; p++) {
            int lin = tid + p * 256;        // 0..1023 : 64 rows x 16 uint4
            int n = lin >> 4, c = lin & 15;
            uint32_t off = (uint32_t)(n * RS2 + c * 8) * 2;
            size_t gi = (size_t)n * 256 + (size_t)kt * 16 + c;
            cp16(dhi + off, Vh4 + gi);
            cp16(dhi + 17408 + off, Vl4 + gi);
        }
    };

    // prologue: Q + chunk 0
    #pragma unroll
    for (int p = 0; p < 4; p++) {
        int lin = tid + p * 256;
        int r = lin >> 3, c = lin & 7;
        uint32_t off = (uint32_t)(r * RS + c * 8) * 2;
        cp16(sb + SQH + off, Qh4 + lin);
        cp16(sb + SQL + off, Ql4 + lin);
    }
    issue_k(0, sb + SKB);
    issue_v(0, sb + SVB);
    CP_COMMIT;
    CP_WAIT0;
    __syncthreads();

    // lane constants
    const int lr = l & 7, sub = l >> 3;
    const int aro = lr + (sub & 1) * 8;            // A ldsm row-in-16
    const uint32_t akc = (uint32_t)((sub >> 1) * 8);
    const int bro = lr + ((l >> 4) << 3);          // B x4 ldsm row-in-16
    const uint32_t bkc = (uint32_t)(((l >> 3) & 1) * 8);
    const int g = l >> 2, q2 = (l & 3) * 2;
    const int row0 = m0 + w * 16 + g, row1 = row0 + 8;

    float oacc[8][4];
    #pragma unroll
    for (int a = 0; a < 8; a++)
        #pragma unroll
        for (int c = 0; c < 4; c++) oacc[a][c] = 0.f;
    float rs0 = 0.f, rs1 = 0.f;

    __nv_bfloat16* aho = g_ah + (size_t)bh * SEQ * SEQ;
    __nv_bfloat16* alo = g_al + (size_t)bh * SEQ * SEQ;

    const uint32_t qh_base = sb + SQH + (uint32_t)((w * 16 + aro) * RS) * 2 + akc * 2;
    const uint32_t ql_base = sb + SQL + (uint32_t)((w * 16 + aro) * RS) * 2 + akc * 2;

    for (int kt = 0; kt < 16; kt++) {
        if (kt + 1 < 16) {
            uint32_t b = (uint32_t)((kt + 1) & 1);
            issue_k(kt + 1, sb + SKB + b * SKSZ);
            issue_v(kt + 1, sb + SVB + b * SVSZ);
            CP_COMMIT;
        }
        const uint32_t KHIb = sb + SKB + (uint32_t)(kt & 1) * SKSZ;
        const uint32_t KLOb = KHIb + 18432;
        const uint32_t VHIb = sb + SVB + (uint32_t)(kt & 1) * SVSZ;
        const uint32_t VLOb = VHIb + 17408;

        // ---- QK: S[16 nt][4] over this 128-col chunk ----
        float sacc[16][4];
        #pragma unroll
        for (int a = 0; a < 16; a++)
            #pragma unroll
            for (int c = 0; c < 4; c++) sacc[a][c] = 0.f;

        #pragma unroll
        for (int ks = 0; ks < 4; ks++) {
            uint32_t ah[4], al[4];
            ldsm_x4(ah, qh_base + (uint32_t)(ks * 16) * 2);
            ldsm_x4(al, ql_base + (uint32_t)(ks * 16) * 2);
            #pragma unroll
            for (int np = 0; np < 8; np++) {
                uint32_t off = (uint32_t)((np * 16 + bro) * RS) * 2 + (bkc + ks * 16) * 2;
                uint32_t bh4[4], bl4[4];
                ldsm_x4(bh4, KHIb + off);
                ldsm_x4(bl4, KLOb + off);
                mma2(sacc[2 * np], ah, bh4[0], bh4[1]);
                mma2(sacc[2 * np], ah, bl4[0], bl4[1]);
                mma2(sacc[2 * np], al, bh4[0], bh4[1]);
                mma2(sacc[2 * np + 1], ah, bh4[2], bh4[3]);
                mma2(sacc[2 * np + 1], ah, bl4[2], bl4[3]);
                mma2(sacc[2 * np + 1], al, bh4[2], bh4[3]);
            }
        }

        // ---- exp + mask + p store + AV (per 16-wide kstep) ----
        #pragma unroll
        for (int t = 0; t < 8; t++) {
            uint32_t ahf[4], alf[4];
            #pragma unroll
            for (int h = 0; h < 2; h++) {
                int nt = 2 * t + h;
                uint32_t w0 = g_mbits[(size_t)row0 * 64 + kt * 4 + (nt >> 2)];
                uint32_t w1 = g_mbits[(size_t)row1 * 64 + kt * 4 + (nt >> 2)];
                int cb = (nt & 3) * 8 + q2;
                float e0 = ((w0 >> cb) & 1)       ? __expf(sacc[nt][0]) : 0.f;
                float e1 = ((w0 >> (cb + 1)) & 1) ? __expf(sacc[nt][1]) : 0.f;
                float e2 = ((w1 >> cb) & 1)       ? __expf(sacc[nt][2]) : 0.f;
                float e3 = ((w1 >> (cb + 1)) & 1) ? __expf(sacc[nt][3]) : 0.f;
                rs0 += e0 + e1;
                rs1 += e2 + e3;
                uint32_t h01, l01, h23, l23;
                pack2(e0, e1, h01, l01);
                pack2(e2, e3, h23, l23);
                size_t o0 = (size_t)row0 * SEQ + kt * 128 + nt * 8 + q2;
                size_t o1 = (size_t)row1 * SEQ + kt * 128 + nt * 8 + q2;
                *(uint32_t*)&aho[o0] = h01;
                *(uint32_t*)&alo[o0] = l01;
                *(uint32_t*)&aho[o1] = h23;
                *(uint32_t*)&alo[o1] = l23;
                ahf[2 * h] = h01; ahf[2 * h + 1] = h23;
                alf[2 * h] = l01; alf[2 * h + 1] = l23;
            }
            // AV for kstep t
            #pragma unroll
            for (int nv = 0; nv < 4; nv++) {
                uint32_t off = (uint32_t)((nv * 16 + bro) * RS2) * 2 + (bkc + t * 16) * 2;
                uint32_t vh4[4], vl4[4];
                ldsm_x4(vh4, VHIb + off);
                ldsm_x4(vl4, VLOb + off);
                mma2(oacc[2 * nv], ahf, vh4[0], vh4[1]);
                mma2(oacc[2 * nv], ahf, vl4[0], vl4[1]);
                mma2(oacc[2 * nv], alf, vh4[0], vh4[1]);
                mma2(oacc[2 * nv + 1], ahf, vh4[2], vh4[3]);
                mma2(oacc[2 * nv + 1], ahf, vl4[2], vl4[3]);
                mma2(oacc[2 * nv + 1], alf, vh4[2], vh4[3]);
            }
        }

        CP_WAIT0;
        __syncthreads();
    }

    // row sums -> inv (quad butterfly keeps value in all lanes)
    rs0 += __shfl_xor_sync(0xffffffffu, rs0, 1);
    rs0 += __shfl_xor_sync(0xffffffffu, rs0, 2);
    rs1 += __shfl_xor_sync(0xffffffffu, rs1, 1);
    rs1 += __shfl_xor_sync(0xffffffffu, rs1, 2);
    const float inv0 = 1.0f / rs0, inv1 = 1.0f / rs1;
    if ((l & 3) == 0) {
        sinv[w * 16 + g] = inv0;
        sinv[w * 16 + g + 8] = inv1;
    }

    // out = oacc * inv
    float* ob = out + ((size_t)bh * SEQ) * DIM;
    #pragma unroll
    for (int nv = 0; nv < 8; nv++) {
        *(float2*)&ob[(size_t)row0 * DIM + nv * 8 + q2] =
            make_float2(oacc[nv][0] * inv0, oacc[nv][1] * inv0);
        *(float2*)&ob[(size_t)row1 * DIM + nv * 8 + q2] =
            make_float2(oacc[nv][2] * inv1, oacc[nv][3] * inv1);
    }

    __syncthreads();   // sinv + this block's p stores visible block-wide

    // tail: attn strip = (p_hi + p_lo) * inv   (reads are L2-hot)
    const uint4* ph4 = (const uint4*)(g_ah + ((size_t)bh * SEQ + m0) * SEQ);
    const uint4* pl4 = (const uint4*)(g_al + ((size_t)bh * SEQ + m0) * SEQ);
    float* arow = attn + ((size_t)bh * SEQ + m0) * SEQ;
    #pragma unroll 4
    for (int i = tid; i < 128 * 256; i += 256) {
        int r = i >> 8, c = i & 255;
        uint4 hh = ph4[i];
        uint4 ll = pl4[i];
        float iv = sinv[r];
        float2 a0 = pairval(hh.x, ll.x, iv);
        float2 a1 = pairval(hh.y, ll.y, iv);
        float2 a2 = pairval(hh.z, ll.z, iv);
        float2 a3 = pairval(hh.w, ll.w, iv);
        size_t o = (size_t)r * SEQ + c * 8;
        *(float4*)&arow[o]     = make_float4(a0.x, a0.y, a1.x, a1.y);
        *(float4*)&arow[o + 4] = make_float4(a2.x, a2.y, a3.x, a3.y);
    }
}

// ---------------- launch ----------------
extern "C" void kernel_launch(void* const* d_in, const int* in_sizes, int n_in,
                              void* d_out, int out_size) {
    const float* Q    = (const float*)d_in[0];
    const float* K    = (const float*)d_in[1];
    const float* V    = (const float*)d_in[2];
    const int*   mask = (const int*)d_in[3];

    float* out  = (float*)d_out;                      // [B,H,S,D]
    float* attn = out + (size_t)NBH * SEQ * DIM;      // [B,H,S,S]

    constexpr int FA_SMEM = 180224;
    cudaFuncSetAttribute(fa_strip, cudaFuncAttributeMaxDynamicSharedMemorySize, FA_SMEM);

    __nv_bfloat16 *qh, *ql, *kh, *kl;
    cudaGetSymbolAddress((void**)&qh, g_qh);
    cudaGetSymbolAddress((void**)&ql, g_ql);
    cudaGetSymbolAddress((void**)&kh, g_kh);
    cudaGetSymbolAddress((void**)&kl, g_kl);

    mask_compress<<<SEQ * (SEQ / 32) / 256, 256>>>(mask);

    const int nsplit = (int)((size_t)NBH * SEQ * DIM / 4 / 256);
    split_prep<<<nsplit, 256>>>(Q, qh, ql, 0.125f);
    split_prep<<<nsplit, 256>>>(K, kh, kl, 1.0f);

    dim3 g0(SEQ / 128, NBH);
    vt_prep<<<g0, 256>>>(V);

    dim3 g1(SEQ / 128, NBH);
    fa_strip<<<g1, 256, FA_SMEM>>>(attn, out);
}

// round 9
// speedup vs baseline: 1.3905x; 1.3905x over previous
#include <cuda_runtime.h>
#include <cuda_bf16.h>
#include <cstdint>

#define SEQ 2048
#define DIM 64
#define NBH 32   // B*H
#define RS 72    // smem row stride in bf16 (144B, conflict-free ldmatrix)

// Scratch (device globals; no allocs allowed)
__device__ __nv_bfloat16 g_qh[(size_t)NBH * SEQ * DIM];
__device__ __nv_bfloat16 g_ql[(size_t)NBH * SEQ * DIM];
__device__ __nv_bfloat16 g_kh[(size_t)NBH * SEQ * DIM];
__device__ __nv_bfloat16 g_kl[(size_t)NBH * SEQ * DIM];
__device__ __nv_bfloat16 g_vt_hi[(size_t)NBH * DIM * SEQ];
__device__ __nv_bfloat16 g_vt_lo[(size_t)NBH * DIM * SEQ];
__device__ __nv_bfloat16 g_ah[(size_t)NBH * SEQ * SEQ];   // unnormalized exp, hi
__device__ __nv_bfloat16 g_al[(size_t)NBH * SEQ * SEQ];   // unnormalized exp, lo
__device__ float    g_inv[(size_t)NBH * SEQ];
__device__ uint32_t g_mbits[(size_t)SEQ * (SEQ / 32)];

// ---------------- helpers ----------------
__device__ __forceinline__ uint32_t smem_u32(const void* p) {
    uint32_t a;
    asm("{ .reg .u64 t; cvta.to.shared.u64 t, %1; cvt.u32.u64 %0, t; }" : "=r"(a) : "l"(p));
    return a;
}
__device__ __forceinline__ void ldsm_x4(uint32_t r[4], uint32_t addr) {
    asm volatile("ldmatrix.sync.aligned.m8n8.x4.shared.b16 {%0,%1,%2,%3}, [%4];"
        : "=r"(r[0]), "=r"(r[1]), "=r"(r[2]), "=r"(r[3]) : "r"(addr));
}
__device__ __forceinline__ void ldsm_x2(uint32_t r[2], uint32_t addr) {
    asm volatile("ldmatrix.sync.aligned.m8n8.x2.shared.b16 {%0,%1}, [%2];"
        : "=r"(r[0]), "=r"(r[1]) : "r"(addr));
}
__device__ __forceinline__ void mma16816(float c[4], const uint32_t a[4], const uint32_t b[2]) {
    asm volatile(
        "mma.sync.aligned.m16n8k16.row.col.f32.bf16.bf16.f32 "
        "{%0,%1,%2,%3}, {%4,%5,%6,%7}, {%8,%9}, {%0,%1,%2,%3};"
        : "+f"(c[0]), "+f"(c[1]), "+f"(c[2]), "+f"(c[3])
        : "r"(a[0]), "r"(a[1]), "r"(a[2]), "r"(a[3]), "r"(b[0]), "r"(b[1]));
}
__device__ __forceinline__ void cp16(uint32_t dst, const void* src) {
    asm volatile("{ .reg .u64 g; cvta.to.global.u64 g, %1; cp.async.cg.shared.global [%0], [g], 16; }"
        :: "r"(dst), "l"(src) : "memory");
}
#define CP_COMMIT asm volatile("cp.async.commit_group;" ::: "memory")
#define CP_WAIT0  asm volatile("cp.async.wait_group 0;" ::: "memory")

// FMA-pipe 2^x: rint + deg-6 Taylor for 2^f (|f|<=0.5, rel err ~1.2e-7) + exponent scale.
__device__ __forceinline__ float fexp2(float x) {
    float n = rintf(x);
    float f = x - n;
    float p = 0.00015403530393381609f;
    p = fmaf(p, f, 0.0013333558146428443f);
    p = fmaf(p, f, 0.009618129107628477f);
    p = fmaf(p, f, 0.05550410866482158f);
    p = fmaf(p, f, 0.2402265069591007f);
    p = fmaf(p, f, 0.6931471805599453f);
    p = fmaf(p, f, 1.0f);
    float s = __int_as_float(((int)n + 127) << 23);
    return p * s;
}

__device__ __forceinline__ void split4(float4 v, uint32_t& h01, uint32_t& h23,
                                       uint32_t& l01, uint32_t& l23) {
    __nv_bfloat16 h0 = __float2bfloat16_rn(v.x);
    __nv_bfloat16 h1 = __float2bfloat16_rn(v.y);
    __nv_bfloat16 h2 = __float2bfloat16_rn(v.z);
    __nv_bfloat16 h3 = __float2bfloat16_rn(v.w);
    __nv_bfloat16 q0 = __float2bfloat16_rn(v.x - __bfloat162float(h0));
    __nv_bfloat16 q1 = __float2bfloat16_rn(v.y - __bfloat162float(h1));
    __nv_bfloat16 q2 = __float2bfloat16_rn(v.z - __bfloat162float(h2));
    __nv_bfloat16 q3 = __float2bfloat16_rn(v.w - __bfloat162float(h3));
    h01 = (uint32_t)__bfloat16_as_ushort(h0) | ((uint32_t)__bfloat16_as_ushort(h1) << 16);
    h23 = (uint32_t)__bfloat16_as_ushort(h2) | ((uint32_t)__bfloat16_as_ushort(h3) << 16);
    l01 = (uint32_t)__bfloat16_as_ushort(q0) | ((uint32_t)__bfloat16_as_ushort(q1) << 16);
    l23 = (uint32_t)__bfloat16_as_ushort(q2) | ((uint32_t)__bfloat16_as_ushort(q3) << 16);
}
__device__ __forceinline__ void pack2(float a, float b, uint32_t& h, uint32_t& lo) {
    __nv_bfloat16 h0 = __float2bfloat16_rn(a), h1 = __float2bfloat16_rn(b);
    __nv_bfloat16 l0 = __float2bfloat16_rn(a - __bfloat162float(h0));
    __nv_bfloat16 l1 = __float2bfloat16_rn(b - __bfloat162float(h1));
    h  = (uint32_t)__bfloat16_as_ushort(h0) | ((uint32_t)__bfloat16_as_ushort(h1) << 16);
    lo = (uint32_t)__bfloat16_as_ushort(l0) | ((uint32_t)__bfloat16_as_ushort(l1) << 16);
}
__device__ __forceinline__ float2 pairval(uint32_t h, uint32_t l, float iv) {
    float2 fh = __bfloat1622float2(*(__nv_bfloat162*)&h);
    float2 fl = __bfloat1622float2(*(__nv_bfloat162*)&l);
    return make_float2((fh.x + fl.x) * iv, (fh.y + fl.y) * iv);
}

// ---------------- Kernel A: mask -> bitmask ----------------
__global__ __launch_bounds__(256) void mask_compress(const int* __restrict__ mask) {
    int w = blockIdx.x * 256 + threadIdx.x;
    const int4* m4 = (const int4*)mask + (size_t)w * 8;
    uint32_t b = 0;
    #pragma unroll
    for (int i = 0; i < 8; i++) {
        int4 v = m4[i];
        b |= (uint32_t)(v.x != 0) << (i * 4 + 0);
        b |= (uint32_t)(v.y != 0) << (i * 4 + 1);
        b |= (uint32_t)(v.z != 0) << (i * 4 + 2);
        b |= (uint32_t)(v.w != 0) << (i * 4 + 3);
    }
    g_mbits[w] = b;
}

// ---------------- Kernel B: fp32 -> bf16 hi/lo (scaled) ----------------
__global__ __launch_bounds__(256) void split_prep(const float* __restrict__ X,
                                                  __nv_bfloat16* __restrict__ hi,
                                                  __nv_bfloat16* __restrict__ lo,
                                                  float scale) {
    size_t i = (size_t)blockIdx.x * 256 + threadIdx.x;
    float4 v = ((const float4*)X)[i];
    v.x *= scale; v.y *= scale; v.z *= scale; v.w *= scale;
    uint32_t h01, h23, l01, l23;
    split4(v, h01, h23, l01, l23);
    ((uint2*)hi)[i] = make_uint2(h01, h23);
    ((uint2*)lo)[i] = make_uint2(l01, l23);
}

// ---------------- Kernel C: V -> Vt (bf16 hi/lo, [bh][n][k]) ----------------
__global__ __launch_bounds__(256) void vt_prep(const float* __restrict__ V) {
    __shared__ float tile[128][DIM + 1];
    const int bh = blockIdx.y;
    const int k0 = blockIdx.x * 128;
    const int tid = threadIdx.x;

    const float4* V4 = (const float4*)(V + ((size_t)bh * SEQ + k0) * DIM);
    #pragma unroll
    for (int p = 0; p < 8; p++) {
        int lin = tid + p * 256;
        int r = lin >> 4, j = lin & 15;
        float4 v = V4[lin];
        tile[r][j * 4 + 0] = v.x; tile[r][j * 4 + 1] = v.y;
        tile[r][j * 4 + 2] = v.z; tile[r][j * 4 + 3] = v.w;
    }
    __syncthreads();
    #pragma unroll
    for (int p = 0; p < 32; p++) {
        int lin = tid + p * 256;
        int n = lin >> 7, k = lin & 127;
        float x = tile[k][n];
        __nv_bfloat16 h = __float2bfloat16_rn(x);
        __nv_bfloat16 l = __float2bfloat16_rn(x - __bfloat162float(h));
        size_t o = ((size_t)bh * DIM + n) * SEQ + k0 + k;
        g_vt_hi[o] = h;
        g_vt_lo[o] = l;
    }
}

// ---- K chunk loader for qk strip ----
__device__ __forceinline__ void issue_k(uint32_t dhi, uint32_t dlo,
                                        const uint4* Kh4, const uint4* Kl4,
                                        int kt, int tid) {
    const uint4* kh = Kh4 + (size_t)kt * 128 * 8;
    const uint4* kl = Kl4 + (size_t)kt * 128 * 8;
    #pragma unroll
    for (int p = 0; p < 4; p++) {
        int lin = tid + p * 256;
        int r = lin >> 3, c = lin & 7;
        uint32_t off = (uint32_t)(r * RS + c * 8) * 2;
        cp16(dhi + off, kh + lin);
        cp16(dlo + off, kl + lin);
    }
}

// ---------------- Kernel D: row-strip QK + exp2 + rowsums -------------------
// Q is pre-scaled by 0.125*log2e so MMA produces S*log2e; p = 2^(S*log2e) = exp(S).
__global__ __launch_bounds__(256, 2) void qk_exp_strip() {
    extern __shared__ char sm[];
    __shared__ float spsum[128];
    const uint32_t sb = smem_u32(sm);
    const int tid = threadIdx.x, wid = tid >> 5, l = tid & 31;
    const int m0 = blockIdx.x * 128, bh = blockIdx.y;

    if (tid < 128) spsum[tid] = 0.f;

    constexpr uint32_t QHI = 0, QLO = 18432, KB = 36864, KBSZ = 36864;

    const uint4* Qh4 = (const uint4*)(g_qh + ((size_t)bh * SEQ + m0) * DIM);
    const uint4* Ql4 = (const uint4*)(g_ql + ((size_t)bh * SEQ + m0) * DIM);
    const uint4* Kh4 = (const uint4*)(g_kh + (size_t)bh * SEQ * DIM);
    const uint4* Kl4 = (const uint4*)(g_kl + (size_t)bh * SEQ * DIM);

    // prologue: Q tiles + K chunk 0
    #pragma unroll
    for (int p = 0; p < 4; p++) {
        int lin = tid + p * 256;
        int r = lin >> 3, c = lin & 7;
        uint32_t off = (uint32_t)(r * RS + c * 8) * 2;
        cp16(sb + QHI + off, Qh4 + lin);
        cp16(sb + QLO + off, Ql4 + lin);
    }
    CP_COMMIT;
    issue_k(sb + KB, sb + KB + 18432, Kh4, Kl4, 0, tid);
    CP_COMMIT;
    CP_WAIT0;
    __syncthreads();

    const int wm = wid >> 2, wn = wid & 3;
    const int mbase = wm * 64, nbase = wn * 32;
    const int lr = l & 7, sub = l >> 3;
    const int arow_lane = lr + (sub & 1) * 8;
    const uint32_t akc = (uint32_t)((sub >> 1) * 8);
    const uint32_t bkc = (uint32_t)((sub & 1) * 8);
    const int g = l >> 2, q2 = (l & 3) * 2;

    float rs[4][2] = {};
    __nv_bfloat16* aho = g_ah + (size_t)bh * SEQ * SEQ;
    __nv_bfloat16* alo = g_al + (size_t)bh * SEQ * SEQ;

    for (int kt = 0; kt < 16; kt++) {
        if (kt + 1 < 16) {
            uint32_t b = (uint32_t)((kt + 1) & 1) * KBSZ;
            issue_k(sb + KB + b, sb + KB + b + 18432, Kh4, Kl4, kt + 1, tid);
            CP_COMMIT;
        }
        const uint32_t KHIb = sb + KB + (uint32_t)(kt & 1) * KBSZ;
        const uint32_t KLOb = KHIb + 18432;

        float acc[4][4][4];
        #pragma unroll
        for (int a = 0; a < 4; a++)
            #pragma unroll
            for (int b = 0; b < 4; b++)
                #pragma unroll
                for (int c = 0; c < 4; c++) acc[a][b][c] = 0.f;

        #pragma unroll
        for (int ks = 0; ks < 4; ks++) {
            uint32_t ah[4][4], al[4][4];
            #pragma unroll
            for (int mt = 0; mt < 4; mt++) {
                int row = mbase + mt * 16 + arow_lane;
                uint32_t off = (uint32_t)(row * RS) * 2 + (akc + ks * 16) * 2;
                ldsm_x4(ah[mt], sb + QHI + off);
                ldsm_x4(al[mt], sb + QLO + off);
            }
            #pragma unroll
            for (int nt = 0; nt < 4; nt++) {
                int rowN = nbase + nt * 8 + lr;
                uint32_t off = (uint32_t)(rowN * RS) * 2 + (bkc + ks * 16) * 2;
                uint32_t bhf[2], blf[2];
                ldsm_x2(bhf, KHIb + off);
                ldsm_x2(blf, KLOb + off);
                #pragma unroll
                for (int mt = 0; mt < 4; mt++) {
                    mma16816(acc[mt][nt], ah[mt], bhf);
                    mma16816(acc[mt][nt], ah[mt], blf);
                    mma16816(acc[mt][nt], al[mt], bhf);
                }
            }
        }

        // epilogue: mask + 2^x (FMA pipe) + bf16 hi/lo stores + register row sums
        #pragma unroll
        for (int mt = 0; mt < 4; mt++) {
            int rl0 = mbase + mt * 16 + g;
            int row0 = m0 + rl0;
            uint32_t w0 = g_mbits[(size_t)row0 * 64 + kt * 4 + wn];
            uint32_t w1 = g_mbits[(size_t)(row0 + 8) * 64 + kt * 4 + wn];
            #pragma unroll
            for (int nt = 0; nt < 4; nt++) {
                int cb = nt * 8 + q2;
                float e0 = ((w0 >> cb) & 1)       ? fexp2(acc[mt][nt][0]) : 0.f;
                float e1 = ((w0 >> (cb + 1)) & 1) ? fexp2(acc[mt][nt][1]) : 0.f;
                float e2 = ((w1 >> cb) & 1)       ? fexp2(acc[mt][nt][2]) : 0.f;
                float e3 = ((w1 >> (cb + 1)) & 1) ? fexp2(acc[mt][nt][3]) : 0.f;
                rs[mt][0] += e0 + e1;
                rs[mt][1] += e2 + e3;
                size_t o0 = (size_t)row0 * SEQ + kt * 128 + nbase + cb;
                size_t o1 = o0 + (size_t)8 * SEQ;
                uint32_t h01, l01, h23, l23;
                pack2(e0, e1, h01, l01);
                pack2(e2, e3, h23, l23);
                *(uint32_t*)&aho[o0] = h01;
                *(uint32_t*)&alo[o0] = l01;
                *(uint32_t*)&aho[o1] = h23;
                *(uint32_t*)&alo[o1] = l23;
            }
        }

        if (kt + 1 < 16) CP_WAIT0;
        __syncthreads();
    }

    // strip row sums -> g_inv
    #pragma unroll
    for (int mt = 0; mt < 4; mt++) {
        float s0 = rs[mt][0], s1 = rs[mt][1];
        s0 += __shfl_xor_sync(0xffffffffu, s0, 1);
        s0 += __shfl_xor_sync(0xffffffffu, s0, 2);
        s1 += __shfl_xor_sync(0xffffffffu, s1, 1);
        s1 += __shfl_xor_sync(0xffffffffu, s1, 2);
        if ((l & 3) == 0) {
            atomicAdd(&spsum[mbase + mt * 16 + g], s0);
            atomicAdd(&spsum[mbase + mt * 16 + g + 8], s1);
        }
    }
    __syncthreads();
    if (tid < 128)
        g_inv[(size_t)bh * SEQ + m0 + tid] = 1.0f / spsum[tid];
}

// ---------------- Kernel E: out = p@V * inv, attn = p * inv -----------------
__global__ __launch_bounds__(256, 2) void attnv_fused(float* __restrict__ attn,
                                                      float* __restrict__ out) {
    extern __shared__ char sm[];
    __shared__ float sinv[128];
    const uint32_t sb = smem_u32(sm);
    const int tid = threadIdx.x, wid = tid >> 5, l = tid & 31;
    const int m0 = blockIdx.x * 128, bh = blockIdx.y;

    if (tid < 128) sinv[tid] = g_inv[(size_t)bh * SEQ + m0 + tid];

    constexpr uint32_t BSZ = 55296, AHI = 0, ALO = 18432, BHI = 36864, BLO = 46080;

    const uint4* Ah4 = (const uint4*)(g_ah + ((size_t)bh * SEQ + m0) * SEQ);
    const uint4* Al4 = (const uint4*)(g_al + ((size_t)bh * SEQ + m0) * SEQ);
    const uint4* Vh4 = (const uint4*)(g_vt_hi + (size_t)bh * DIM * SEQ);
    const uint4* Vl4 = (const uint4*)(g_vt_lo + (size_t)bh * DIM * SEQ);

    const int ar0 = tid >> 3, ac = tid & 7;

    auto issue_chunk = [&](int kt, uint32_t base) {
        #pragma unroll
        for (int p = 0; p < 4; p++) {
            int r = ar0 + p * 32;
            uint32_t off = (uint32_t)(r * RS + ac * 8) * 2;
            size_t gi = (size_t)r * 256 + kt * 8 + ac;
            cp16(sb + base + AHI + off, Ah4 + gi);
            cp16(sb + base + ALO + off, Al4 + gi);
        }
        #pragma unroll
        for (int p = 0; p < 2; p++) {
            int n = ar0 + p * 32;
            uint32_t off = (uint32_t)(n * RS + ac * 8) * 2;
            size_t gi = (size_t)n * 256 + kt * 8 + ac;
            cp16(sb + base + BHI + off, Vh4 + gi);
            cp16(sb + base + BLO + off, Vl4 + gi);
        }
    };

    issue_chunk(0, 0);
    CP_COMMIT;
    CP_WAIT0;
    __syncthreads();

    const int wm = wid >> 1, wn = wid & 1;
    const int mbase = wm * 32, nbase = wn * 32;
    const int lr = l & 7, sub = l >> 3;
    const int arow_lane = lr + (sub & 1) * 8;
    const uint32_t akc = (uint32_t)((sub >> 1) * 8);
    const uint32_t bkc = (uint32_t)((sub & 1) * 8);

    float acc[2][4][4];
    #pragma unroll
    for (int a = 0; a < 2; a++)
        #pragma unroll
        for (int b = 0; b < 4; b++)
            #pragma unroll
            for (int c = 0; c < 4; c++) acc[a][b][c] = 0.f;

    float* arow = attn + ((size_t)bh * SEQ + m0) * SEQ;

    for (int kt = 0; kt < 32; kt++) {
        if (kt + 1 < 32) {
            issue_chunk(kt + 1, (uint32_t)((kt + 1) & 1) * BSZ);
            CP_COMMIT;
        }
        const uint32_t base = (uint32_t)(kt & 1) * BSZ;

        // stream normalized fp32 attn from this chunk's smem copy
        #pragma unroll
        for (int p = 0; p < 4; p++) {
            int r = ar0 + p * 32;
            uint32_t off = (uint32_t)(r * RS + ac * 8) * 2;
            uint4 hh = *(const uint4*)(sm + base + AHI + off);
            uint4 ll = *(const uint4*)(sm + base + ALO + off);
            float iv = sinv[r];
            float2 a0 = pairval(hh.x, ll.x, iv);
            float2 a1 = pairval(hh.y, ll.y, iv);
            float2 a2 = pairval(hh.z, ll.z, iv);
            float2 a3 = pairval(hh.w, ll.w, iv);
            size_t o = (size_t)r * SEQ + kt * 64 + ac * 8;
            *(float4*)&arow[o]     = make_float4(a0.x, a0.y, a1.x, a1.y);
            *(float4*)&arow[o + 4] = make_float4(a2.x, a2.y, a3.x, a3.y);
        }

        #pragma unroll
        for (int ks = 0; ks < 4; ks++) {
            uint32_t ah[2][4], al[2][4];
            #pragma unroll
            for (int mt = 0; mt < 2; mt++) {
                int row = mbase + mt * 16 + arow_lane;
                uint32_t off = (uint32_t)(row * RS) * 2 + (akc + ks * 16) * 2;
                ldsm_x4(ah[mt], sb + base + AHI + off);
                ldsm_x4(al[mt], sb + base + ALO + off);
            }
            #pragma unroll
            for (int nt = 0; nt < 4; nt++) {
                int rowN = nbase + nt * 8 + lr;
                uint32_t off = (uint32_t)(rowN * RS) * 2 + (bkc + ks * 16) * 2;
                uint32_t bhf[2], blf[2];
                ldsm_x2(bhf, sb + base + BHI + off);
                ldsm_x2(blf, sb + base + BLO + off);
                #pragma unroll
                for (int mt = 0; mt < 2; mt++) {
                    mma16816(acc[mt][nt], ah[mt], bhf);
                    mma16816(acc[mt][nt], ah[mt], blf);
                    mma16816(acc[mt][nt], al[mt], bhf);
                }
            }
        }

        if (kt + 1 < 32) CP_WAIT0;
        __syncthreads();
    }

    const int g = l >> 2, q2 = (l & 3) * 2;
    float* ob = out + ((size_t)bh * SEQ + m0) * DIM;
    #pragma unroll
    for (int mt = 0; mt < 2; mt++) {
        int rl = mbase + mt * 16 + g;
        float iv0 = sinv[rl], iv1 = sinv[rl + 8];
        #pragma unroll
        for (int nt = 0; nt < 4; nt++) {
            int col = nbase + nt * 8 + q2;
            *(float2*)&ob[(size_t)rl * DIM + col] =
                make_float2(acc[mt][nt][0] * iv0, acc[mt][nt][1] * iv0);
            *(float2*)&ob[(size_t)(rl + 8) * DIM + col] =
                make_float2(acc[mt][nt][2] * iv1, acc[mt][nt][3] * iv1);
        }
    }
}

// ---------------- launch ----------------
extern "C" void kernel_launch(void* const* d_in, const int* in_sizes, int n_in,
                              void* d_out, int out_size) {
    const float* Q    = (const float*)d_in[0];
    const float* K    = (const float*)d_in[1];
    const float* V    = (const float*)d_in[2];
    const int*   mask = (const int*)d_in[3];

    float* out  = (float*)d_out;                      // [B,H,S,D]
    float* attn = out + (size_t)NBH * SEQ * DIM;      // [B,H,S,S]

    constexpr int STRIP_SMEM = 110592;
    cudaFuncSetAttribute(qk_exp_strip, cudaFuncAttributeMaxDynamicSharedMemorySize, STRIP_SMEM);
    cudaFuncSetAttribute(attnv_fused, cudaFuncAttributeMaxDynamicSharedMemorySize, STRIP_SMEM);

    __nv_bfloat16 *qh, *ql, *kh, *kl;
    cudaGetSymbolAddress((void**)&qh, g_qh);
    cudaGetSymbolAddress((void**)&ql, g_ql);
    cudaGetSymbolAddress((void**)&kh, g_kh);
    cudaGetSymbolAddress((void**)&kl, g_kl);

    mask_compress<<<SEQ * (SEQ / 32) / 256, 256>>>(mask);

    const int nsplit = (int)((size_t)NBH * SEQ * DIM / 4 / 256);
    // Q pre-scaled by (1/8)*log2(e): MMA emits S*log2(e), epilogue uses 2^x.
    split_prep<<<nsplit, 256>>>(Q, qh, ql, 0.125f * 1.4426950408889634f);
    split_prep<<<nsplit, 256>>>(K, kh, kl, 1.0f);

    dim3 g0(SEQ / 128, NBH);
    vt_prep<<<g0, 256>>>(V);

    dim3 g1(SEQ / 128, NBH);
    qk_exp_strip<<<g1, 256, STRIP_SMEM>>>();

    dim3 g2(SEQ / 128, NBH);
    attnv_fused<<<g2, 256, STRIP_SMEM>>>(attn, out);
}